// round 12
// baseline (speedup 1.0000x reference)
#include <cuda_runtime.h>
#include <cuda_bf16.h>
#include <stdint.h>

#define A_NUM   15
#define H_DIM   34
#define W_DIM   34
#define HW      (H_DIM * W_DIM)          // 1156
#define NANCH   (A_NUM * HW)             // 17340
#define MAXC    3000
#define VWORDS  47                        // ceil(3000/64)
#define TOPN    300
#define BINS    16384
#define BCAP    32
#define FASTN   1024                      // in-shared NMS window
#define MW      16                        // FASTN/64 mask words per row
#define NBOX    3008

__constant__ float c_AW[15] = {9.232984f, 16.0f, 27.712813f, 18.465969f, 32.0f,
    55.425626f, 36.931937f, 64.0f, 110.851252f, 73.863875f, 128.0f,
    221.702503f, 147.72775f, 256.0f, 443.405007f};
__constant__ float c_AH[15] = {27.72668f, 16.0f, 9.237604f, 55.453359f, 32.0f,
    18.475209f, 110.906719f, 64.0f, 36.950417f, 221.813438f, 128.0f,
    73.900834f, 443.626876f, 256.0f, 147.801669f};
__constant__ float c_STD[4]  = {0.12677f, 0.095741f, 0.3173f, 0.281042f};
__constant__ float c_MEAN[4] = {0.000437f, 0.002586f, -0.123953f, -0.081469f};

// ---- scratch (device globals; zero at module load, self-restored each run) ----
__device__ float4 g_boxes[NANCH];
__device__ float2 g_scores[NANCH];
__device__ int    g_bincnt[BINS];                       // ZERO on entry (restored by k_nms)
__device__ unsigned long long g_binkeys[BINS * BCAP];
__device__ float4 g_cboxes[NBOX];
__device__ float2 g_cscores[NBOX];
__device__ unsigned long long g_validbits[VWORDS];      // ZERO on entry (restored by k_nms)
__device__ unsigned long long g_mask[FASTN * MW];       // fully rewritten each run

// ---------------------------------------------------------------
__global__ void k_prepare(const float* __restrict__ cls,
                          const float* __restrict__ pred,
                          const int*   __restrict__ im_info) {
    int n = blockIdx.x * blockDim.x + threadIdx.x;
    if (n >= NANCH) return;
    int a = n % A_NUM;
    int q = n / A_NUM;           // q = h*W + w
    int w = q % W_DIM;
    int h = q / W_DIM;

    float AW = c_AW[a], AH = c_AH[a];
    float xm = __fmul_rn(-0.5f, __fsub_rn(AW, 1.0f));
    float ym = __fmul_rn(-0.5f, __fsub_rn(AH, 1.0f));
    float shift_x = (float)(w * 8);
    float shift_y = (float)(h * 8);

    float x1a = __fadd_rn(shift_x, xm);
    float y1a = __fadd_rn(shift_y, ym);
    float x2a = __fsub_rn(shift_x, xm);
    float y2a = __fsub_rn(shift_y, ym);

    float widths  = __fadd_rn(__fsub_rn(x2a, x1a), 1.0f);
    float heights = __fadd_rn(__fsub_rn(y2a, y1a), 1.0f);
    float ctr_x = __fadd_rn(x1a, __fmul_rn(0.5f, __fsub_rn(widths, 1.0f)));
    float ctr_y = __fadd_rn(y1a, __fmul_rn(0.5f, __fsub_rn(heights, 1.0f)));

    float d0 = __fadd_rn(__fmul_rn(pred[(a*4+0)*HW + q], c_STD[0]), c_MEAN[0]);
    float d1 = __fadd_rn(__fmul_rn(pred[(a*4+1)*HW + q], c_STD[1]), c_MEAN[1]);
    float d2 = __fadd_rn(__fmul_rn(pred[(a*4+2)*HW + q], c_STD[2]), c_MEAN[2]);
    float d3 = __fadd_rn(__fmul_rn(pred[(a*4+3)*HW + q], c_STD[3]), c_MEAN[3]);

    float pcx = __fadd_rn(__fmul_rn(d0, widths),  ctr_x);
    float pcy = __fadd_rn(__fmul_rn(d1, heights), ctr_y);
    float pw  = __fmul_rn(expf(d2), widths);
    float ph  = __fmul_rn(expf(d3), heights);

    float hwid = __fmul_rn(0.5f, __fsub_rn(pw, 1.0f));
    float hhei = __fmul_rn(0.5f, __fsub_rn(ph, 1.0f));
    float bx1 = __fsub_rn(pcx, hwid);
    float by1 = __fsub_rn(pcy, hhei);
    float bx2 = __fadd_rn(pcx, hwid);
    float by2 = __fadd_rn(pcy, hhei);

    float ow = __fsub_rn((float)im_info[1], 1.0f);
    float oh = __fsub_rn((float)im_info[0], 1.0f);
    bx1 = fminf(fmaxf(bx1, 0.0f), ow);
    by1 = fminf(fmaxf(by1, 0.0f), oh);
    bx2 = fminf(fmaxf(bx2, 0.0f), ow);
    by2 = fminf(fmaxf(by2, 0.0f), oh);

    float ws = __fadd_rn(__fsub_rn(bx2, bx1), 1.0f);
    float hs = __fadd_rn(__fsub_rn(by2, by1), 1.0f);

    float s0 = cls[(0*A_NUM + a)*HW + q];
    float s1 = cls[(1*A_NUM + a)*HW + q];

    g_boxes[n]  = make_float4(bx1, by1, bx2, by2);
    g_scores[n] = make_float2(s0, s1);

    bool keep = (s1 > 0.2f) && ((ws >= 6.16056f) || (hs >= 6.16056f));
    if (keep) {
        unsigned long long key =
              (((unsigned long long)__float_as_uint(s1)) << 32)
            | (unsigned long long)(0xFFFFFFFFu - (unsigned)n);
        int bin = (int)__fmul_rn(s1, 16384.0f);     // monotone in s1
        if (bin > BINS - 1) bin = BINS - 1;
        int slot = atomicAdd(&g_bincnt[bin], 1);
        if (slot < BCAP) g_binkeys[bin * BCAP + slot] = key;
    }
}

// ---------------------------------------------------------------
// 64 blocks x 1024 threads. Each block redundantly computes the full
// 16384-bin suffix scan in shared, then scatters its 256-bin slice.
__global__ void k_rankscatter() {
    __shared__ int ssum[1024];
    __shared__ int sblk[256];       // suffix for this block's scatter bins
    int tid = threadIdx.x;
    int blk = blockIdx.x;

    // full scan: thread t covers bins [t*16, t*16+16)
    int base = tid * 16;
    int cnts[16];
    int s = 0;
    #pragma unroll
    for (int k = 0; k < 16; ++k) {
        cnts[k] = g_bincnt[base + k];
        s += cnts[k];
    }
    ssum[tid] = s;
    __syncthreads();
    for (int off = 1; off < 1024; off <<= 1) {
        int v = ssum[tid];
        int add = (tid + off < 1024) ? ssum[tid + off] : 0;
        __syncthreads();
        ssum[tid] = v + add;
        __syncthreads();
    }
    int acc = (tid < 1023) ? ssum[tid + 1] : 0;
    int sufk[16];
    #pragma unroll
    for (int k = 15; k >= 0; --k) {
        sufk[k] = acc;
        acc += cnts[k];
    }
    int lo = blk * 16;                     // scan-thread range [lo, lo+16)
    if (tid >= lo && tid < lo + 16) {
        int off = (tid - lo) * 16;
        #pragma unroll
        for (int k = 0; k < 16; ++k) sblk[off + k] = sufk[k];
    }
    __syncthreads();

    // scatter: threads 0..255, bin b = blk*256 + tid
    if (tid >= 256) return;
    int b = blk * 256 + tid;
    int c = g_bincnt[b];
    if (c <= 0) return;
    if (c > BCAP) c = BCAP;
    int excl = sblk[tid];
    if (excl >= MAXC) return;
    const unsigned long long* bl = &g_binkeys[b * BCAP];
    for (int i = 0; i < c; ++i) {
        unsigned long long ki = bl[i];
        int r = excl;
        for (int j = 0; j < c; ++j)
            r += (bl[j] > ki) ? 1 : 0;
        if (r < MAXC) {
            unsigned n = 0xFFFFFFFFu - (unsigned)(ki & 0xFFFFFFFFull);
            g_cboxes[r]  = g_boxes[n];
            g_cscores[r] = g_scores[n];
            atomicOr(&g_validbits[r >> 6], 1ull << (r & 63));
        }
    }
}

// ---------------------------------------------------------------
// ballot-parallel suppression mask: warp computes one (row, 64-col word);
// grid (16 col-words, 32 row-halfblocks), 4 rows per warp.
__global__ void k_nmsmask1024() {
    int cw  = blockIdx.x;          // column word 0..15
    int rb  = blockIdx.y;          // 32-row block 0..31
    int lane = threadIdx.x & 31;
    int wid  = threadIdx.x >> 5;   // 0..7
    int col0 = cw * 64;

    if (rb > 2 * cw + 1) {         // all rows strictly below diagonal word
        if (threadIdx.x < 32)
            g_mask[(rb * 32 + threadIdx.x) * MW + cw] = 0ull;
        return;
    }

    __shared__ float4 sbox[64];
    if (threadIdx.x < 64) sbox[threadIdx.x] = g_cboxes[col0 + threadIdx.x];
    __syncthreads();

    float4 bj0 = sbox[lane];
    float4 bj1 = sbox[lane + 32];
    float areaj0 = __fmul_rn(__fsub_rn(bj0.z, bj0.x), __fsub_rn(bj0.w, bj0.y));
    float areaj1 = __fmul_rn(__fsub_rn(bj1.z, bj1.x), __fsub_rn(bj1.w, bj1.y));

    #pragma unroll
    for (int rr = 0; rr < 4; ++rr) {
        int i = rb * 32 + rr * 8 + wid;
        float4 bi = g_cboxes[i];   // uniform across warp (broadcast)
        float areai = __fmul_rn(__fsub_rn(bi.z, bi.x), __fsub_rn(bi.w, bi.y));

        float iw0 = fmaxf(__fsub_rn(fminf(bi.z, bj0.z), fmaxf(bi.x, bj0.x)), 0.0f);
        float ih0 = fmaxf(__fsub_rn(fminf(bi.w, bj0.w), fmaxf(bi.y, bj0.y)), 0.0f);
        float in0 = __fmul_rn(iw0, ih0);
        float de0 = fmaxf(__fsub_rn(__fadd_rn(areai, areaj0), in0), 1e-12f);
        bool s0 = __fdiv_rn(in0, de0) > 0.7f;

        float iw1 = fmaxf(__fsub_rn(fminf(bi.z, bj1.z), fmaxf(bi.x, bj1.x)), 0.0f);
        float ih1 = fmaxf(__fsub_rn(fminf(bi.w, bj1.w), fmaxf(bi.y, bj1.y)), 0.0f);
        float in1 = __fmul_rn(iw1, ih1);
        float de1 = fmaxf(__fsub_rn(__fadd_rn(areai, areaj1), in1), 1e-12f);
        bool s1 = __fdiv_rn(in1, de1) > 0.7f;

        unsigned lo = __ballot_sync(0xFFFFFFFFu, s0);
        unsigned hi = __ballot_sync(0xFFFFFFFFu, s1);
        if (lane == 0) {
            unsigned long long bits =
                (unsigned long long)lo | ((unsigned long long)hi << 32);
            if (i >= col0 + 63)  bits = 0ull;
            else if (i >= col0)  bits &= (~0ull) << (i - col0 + 1);
            g_mask[i * MW + cw] = bits;
        }
    }
}

// ---------------------------------------------------------------
__device__ __forceinline__ bool iou_gt_s(const float4 bi, float areai, const float4 bj) {
    float iw = fmaxf(__fsub_rn(fminf(bi.z, bj.z), fmaxf(bi.x, bj.x)), 0.0f);
    float ih = fmaxf(__fsub_rn(fminf(bi.w, bj.w), fmaxf(bi.y, bj.y)), 0.0f);
    float inter = __fmul_rn(iw, ih);
    float areaj = __fmul_rn(__fsub_rn(bj.z, bj.x), __fsub_rn(bj.w, bj.y));
    float denom = fmaxf(__fsub_rn(__fadd_rn(areai, areaj), inter), 1e-12f);
    return __fdiv_rn(inter, denom) > 0.7f;
}

// ---------------------------------------------------------------
// single-block NMS: fully warp-uniform serial loop (no divergent branches
// in the hot body); mask staged in shared.
__global__ void k_nms(float* __restrict__ out) {
    extern __shared__ unsigned long long smask[];            // FASTN*MW (128KB)
    __shared__ int keptlist[TOPN];
    __shared__ unsigned long long svalid[VWORDS + 1];
    __shared__ int s_cnt;

    int tid = threadIdx.x;

    #pragma unroll
    for (int k = 0; k < MW; ++k)
        smask[k * 1024 + tid] = g_mask[k * 1024 + tid];
    if (tid < VWORDS) svalid[tid] = g_validbits[tid];
    if (tid == VWORDS) svalid[tid] = 0ull;
    __syncthreads();

    if (tid < 32) {
        const unsigned FULL = 0xFFFFFFFFu;
        int t = tid;
        int tm = t & 15;
        // lanes 0..15 own rem words 0..15; lanes 16..31 hold duplicates
        // (accumulate garbage, never shuffled from)
        unsigned long long myrem = (t < MW) ? ~svalid[t] : ~0ull;

        int cnt = 0;
        int w = 0;
        unsigned long long cur = __shfl_sync(FULL, myrem, 0);
        for (;;) {
            unsigned long long avail = ~cur;
            if (avail == 0ull) {                 // uniform branch
                ++w;
                if (w >= MW) break;
                cur = __shfl_sync(FULL, myrem, w);
                continue;
            }
            int b = __ffsll((long long)avail) - 1;
            int i = (w << 6) + b;
            keptlist[cnt] = i;                   // uniform merged store
            cnt++;
            if (cnt >= TOPN) break;              // uniform branch
            myrem |= smask[i * MW + tm];         // all lanes, no branch
            cur |= smask[i * MW + w];            // broadcast LDS
            cur |= 1ull << b;                    // consume bit b
        }

        // deterministic fallback over candidates [FASTN, MAXC) (cold path)
        if (cnt < TOPN) {
            for (int j = FASTN; j < MAXC && cnt < TOPN; ++j) {
                if (!((svalid[j >> 6] >> (j & 63)) & 1ull)) continue;
                float4 bj = g_cboxes[j];
                bool sup = false;
                for (int k = t; k < cnt; k += 32) {
                    float4 bi = g_cboxes[keptlist[k]];
                    float areai = __fmul_rn(__fsub_rn(bi.z, bi.x), __fsub_rn(bi.w, bi.y));
                    if (iou_gt_s(bi, areai, bj)) { sup = true; break; }
                }
                if (!__any_sync(FULL, sup)) {
                    if (t == 0) keptlist[cnt] = j;
                    __syncwarp();
                    cnt++;
                }
            }
        }
        if (t == 0) s_cnt = cnt;
    }
    __syncthreads();

    int cnt = s_cnt;
    // output: proposals [300,5] then scores [300,2]
    for (int r = tid; r < TOPN; r += 1024) {
        if (r < cnt) {
            int idx = keptlist[r];
            float4 bb = g_cboxes[idx];
            float2 sc = g_cscores[idx];
            out[r*5 + 0] = 0.0f;
            out[r*5 + 1] = bb.x;
            out[r*5 + 2] = bb.y;
            out[r*5 + 3] = bb.z;
            out[r*5 + 4] = bb.w;
            out[1500 + r*2 + 0] = sc.x;
            out[1500 + r*2 + 1] = sc.y;
        } else {
            out[r*5 + 0] = 0.0f; out[r*5 + 1] = 0.0f; out[r*5 + 2] = 0.0f;
            out[r*5 + 3] = 0.0f; out[r*5 + 4] = 0.0f;
            out[1500 + r*2 + 0] = 0.0f;
            out[1500 + r*2 + 1] = 0.0f;
        }
    }

    // restore scratch invariant for next graph replay
    #pragma unroll
    for (int k = 0; k < BINS / 1024; ++k)
        g_bincnt[k * 1024 + tid] = 0;
    if (tid < VWORDS) g_validbits[tid] = 0ull;
}

// ---------------------------------------------------------------
extern "C" void kernel_launch(void* const* d_in, const int* in_sizes, int n_in,
                              void* d_out, int out_size) {
    const float* cls     = (const float*)d_in[0];
    const float* pred    = (const float*)d_in[1];
    const int*   im_info = (const int*)d_in[2];
    float* out = (float*)d_out;

    const int NMS_SMEM = FASTN * MW * (int)sizeof(unsigned long long);

    static bool attr_set = false;
    if (!attr_set) {
        cudaFuncSetAttribute(k_nms, cudaFuncAttributeMaxDynamicSharedMemorySize,
                             NMS_SMEM);
        attr_set = true;
    }

    k_prepare<<<68, 256>>>(cls, pred, im_info);
    k_rankscatter<<<64, 1024>>>();
    {
        dim3 grid(MW, 32);
        k_nmsmask1024<<<grid, 256>>>();
    }
    k_nms<<<1, 1024, NMS_SMEM>>>(out);
}

// round 13
// speedup vs baseline: 1.0858x; 1.0858x over previous
#include <cuda_runtime.h>
#include <cuda_bf16.h>
#include <stdint.h>

#define A_NUM   15
#define H_DIM   34
#define W_DIM   34
#define HW      (H_DIM * W_DIM)          // 1156
#define NANCH   (A_NUM * HW)             // 17340
#define MAXC    3000
#define VWORDS  47                        // ceil(3000/64)
#define TOPN    300
#define BINS    16384
#define BCAP    32
#define FASTN   1024                      // in-shared NMS window
#define MW      16                        // FASTN/64 mask words per row
#define NBOX    3008

__constant__ float c_AW[15] = {9.232984f, 16.0f, 27.712813f, 18.465969f, 32.0f,
    55.425626f, 36.931937f, 64.0f, 110.851252f, 73.863875f, 128.0f,
    221.702503f, 147.72775f, 256.0f, 443.405007f};
__constant__ float c_AH[15] = {27.72668f, 16.0f, 9.237604f, 55.453359f, 32.0f,
    18.475209f, 110.906719f, 64.0f, 36.950417f, 221.813438f, 128.0f,
    73.900834f, 443.626876f, 256.0f, 147.801669f};
__constant__ float c_STD[4]  = {0.12677f, 0.095741f, 0.3173f, 0.281042f};
__constant__ float c_MEAN[4] = {0.000437f, 0.002586f, -0.123953f, -0.081469f};

// ---- scratch (device globals; zero at module load, self-restored each run) ----
__device__ float4 g_boxes[NANCH];
__device__ float2 g_scores[NANCH];
__device__ int    g_bincnt[BINS];                       // ZERO on entry (restored by k_nms)
__device__ unsigned long long g_binkeys[BINS * BCAP];
__device__ float4 g_cboxes[NBOX];
__device__ float2 g_cscores[NBOX];
__device__ unsigned long long g_validbits[VWORDS];      // ZERO on entry (restored by k_nms)
__device__ unsigned long long g_mask[FASTN * MW];       // fully rewritten each run

// ---------------------------------------------------------------
__global__ void k_prepare(const float* __restrict__ cls,
                          const float* __restrict__ pred,
                          const int*   __restrict__ im_info) {
    int n = blockIdx.x * blockDim.x + threadIdx.x;
    if (n >= NANCH) return;
    int a = n % A_NUM;
    int q = n / A_NUM;           // q = h*W + w
    int w = q % W_DIM;
    int h = q / W_DIM;

    float AW = c_AW[a], AH = c_AH[a];
    float xm = __fmul_rn(-0.5f, __fsub_rn(AW, 1.0f));
    float ym = __fmul_rn(-0.5f, __fsub_rn(AH, 1.0f));
    float shift_x = (float)(w * 8);
    float shift_y = (float)(h * 8);

    float x1a = __fadd_rn(shift_x, xm);
    float y1a = __fadd_rn(shift_y, ym);
    float x2a = __fsub_rn(shift_x, xm);
    float y2a = __fsub_rn(shift_y, ym);

    float widths  = __fadd_rn(__fsub_rn(x2a, x1a), 1.0f);
    float heights = __fadd_rn(__fsub_rn(y2a, y1a), 1.0f);
    float ctr_x = __fadd_rn(x1a, __fmul_rn(0.5f, __fsub_rn(widths, 1.0f)));
    float ctr_y = __fadd_rn(y1a, __fmul_rn(0.5f, __fsub_rn(heights, 1.0f)));

    float d0 = __fadd_rn(__fmul_rn(pred[(a*4+0)*HW + q], c_STD[0]), c_MEAN[0]);
    float d1 = __fadd_rn(__fmul_rn(pred[(a*4+1)*HW + q], c_STD[1]), c_MEAN[1]);
    float d2 = __fadd_rn(__fmul_rn(pred[(a*4+2)*HW + q], c_STD[2]), c_MEAN[2]);
    float d3 = __fadd_rn(__fmul_rn(pred[(a*4+3)*HW + q], c_STD[3]), c_MEAN[3]);

    float pcx = __fadd_rn(__fmul_rn(d0, widths),  ctr_x);
    float pcy = __fadd_rn(__fmul_rn(d1, heights), ctr_y);
    float pw  = __fmul_rn(expf(d2), widths);
    float ph  = __fmul_rn(expf(d3), heights);

    float hwid = __fmul_rn(0.5f, __fsub_rn(pw, 1.0f));
    float hhei = __fmul_rn(0.5f, __fsub_rn(ph, 1.0f));
    float bx1 = __fsub_rn(pcx, hwid);
    float by1 = __fsub_rn(pcy, hhei);
    float bx2 = __fadd_rn(pcx, hwid);
    float by2 = __fadd_rn(pcy, hhei);

    float ow = __fsub_rn((float)im_info[1], 1.0f);
    float oh = __fsub_rn((float)im_info[0], 1.0f);
    bx1 = fminf(fmaxf(bx1, 0.0f), ow);
    by1 = fminf(fmaxf(by1, 0.0f), oh);
    bx2 = fminf(fmaxf(bx2, 0.0f), ow);
    by2 = fminf(fmaxf(by2, 0.0f), oh);

    float ws = __fadd_rn(__fsub_rn(bx2, bx1), 1.0f);
    float hs = __fadd_rn(__fsub_rn(by2, by1), 1.0f);

    float s0 = cls[(0*A_NUM + a)*HW + q];
    float s1 = cls[(1*A_NUM + a)*HW + q];

    g_boxes[n]  = make_float4(bx1, by1, bx2, by2);
    g_scores[n] = make_float2(s0, s1);

    bool keep = (s1 > 0.2f) && ((ws >= 6.16056f) || (hs >= 6.16056f));
    if (keep) {
        unsigned long long key =
              (((unsigned long long)__float_as_uint(s1)) << 32)
            | (unsigned long long)(0xFFFFFFFFu - (unsigned)n);
        int bin = (int)__fmul_rn(s1, 16384.0f);     // monotone in s1
        if (bin > BINS - 1) bin = BINS - 1;
        int slot = atomicAdd(&g_bincnt[bin], 1);
        if (slot < BCAP) g_binkeys[bin * BCAP + slot] = key;
    }
}

// ---------------------------------------------------------------
// 64 blocks x 1024 threads. Each block redundantly computes the full
// 16384-bin suffix scan in shared, then scatters its 256-bin slice.
__global__ void k_rankscatter() {
    __shared__ int ssum[1024];
    __shared__ int sblk[256];       // suffix for this block's scatter bins
    int tid = threadIdx.x;
    int blk = blockIdx.x;

    int base = tid * 16;
    int cnts[16];
    int s = 0;
    #pragma unroll
    for (int k = 0; k < 16; ++k) {
        cnts[k] = g_bincnt[base + k];
        s += cnts[k];
    }
    ssum[tid] = s;
    __syncthreads();
    for (int off = 1; off < 1024; off <<= 1) {
        int v = ssum[tid];
        int add = (tid + off < 1024) ? ssum[tid + off] : 0;
        __syncthreads();
        ssum[tid] = v + add;
        __syncthreads();
    }
    int acc = (tid < 1023) ? ssum[tid + 1] : 0;
    int sufk[16];
    #pragma unroll
    for (int k = 15; k >= 0; --k) {
        sufk[k] = acc;
        acc += cnts[k];
    }
    int lo = blk * 16;
    if (tid >= lo && tid < lo + 16) {
        int off = (tid - lo) * 16;
        #pragma unroll
        for (int k = 0; k < 16; ++k) sblk[off + k] = sufk[k];
    }
    __syncthreads();

    if (tid >= 256) return;
    int b = blk * 256 + tid;
    int c = g_bincnt[b];
    if (c <= 0) return;
    if (c > BCAP) c = BCAP;
    int excl = sblk[tid];
    if (excl >= MAXC) return;
    const unsigned long long* bl = &g_binkeys[b * BCAP];
    for (int i = 0; i < c; ++i) {
        unsigned long long ki = bl[i];
        int r = excl;
        for (int j = 0; j < c; ++j)
            r += (bl[j] > ki) ? 1 : 0;
        if (r < MAXC) {
            unsigned n = 0xFFFFFFFFu - (unsigned)(ki & 0xFFFFFFFFull);
            g_cboxes[r]  = g_boxes[n];
            g_cscores[r] = g_scores[n];
            atomicOr(&g_validbits[r >> 6], 1ull << (r & 63));
        }
    }
}

// ---------------------------------------------------------------
// ballot-parallel suppression mask: warp computes one (row, 64-col word).
__global__ void k_nmsmask1024() {
    int cw  = blockIdx.x;          // column word 0..15
    int rb  = blockIdx.y;          // 32-row block 0..31
    int lane = threadIdx.x & 31;
    int wid  = threadIdx.x >> 5;   // 0..7
    int col0 = cw * 64;

    if (rb > 2 * cw + 1) {
        if (threadIdx.x < 32)
            g_mask[(rb * 32 + threadIdx.x) * MW + cw] = 0ull;
        return;
    }

    __shared__ float4 sbox[64];
    if (threadIdx.x < 64) sbox[threadIdx.x] = g_cboxes[col0 + threadIdx.x];
    __syncthreads();

    float4 bj0 = sbox[lane];
    float4 bj1 = sbox[lane + 32];
    float areaj0 = __fmul_rn(__fsub_rn(bj0.z, bj0.x), __fsub_rn(bj0.w, bj0.y));
    float areaj1 = __fmul_rn(__fsub_rn(bj1.z, bj1.x), __fsub_rn(bj1.w, bj1.y));

    #pragma unroll
    for (int rr = 0; rr < 4; ++rr) {
        int i = rb * 32 + rr * 8 + wid;
        float4 bi = g_cboxes[i];
        float areai = __fmul_rn(__fsub_rn(bi.z, bi.x), __fsub_rn(bi.w, bi.y));

        float iw0 = fmaxf(__fsub_rn(fminf(bi.z, bj0.z), fmaxf(bi.x, bj0.x)), 0.0f);
        float ih0 = fmaxf(__fsub_rn(fminf(bi.w, bj0.w), fmaxf(bi.y, bj0.y)), 0.0f);
        float in0 = __fmul_rn(iw0, ih0);
        float de0 = fmaxf(__fsub_rn(__fadd_rn(areai, areaj0), in0), 1e-12f);
        bool s0 = __fdiv_rn(in0, de0) > 0.7f;

        float iw1 = fmaxf(__fsub_rn(fminf(bi.z, bj1.z), fmaxf(bi.x, bj1.x)), 0.0f);
        float ih1 = fmaxf(__fsub_rn(fminf(bi.w, bj1.w), fmaxf(bi.y, bj1.y)), 0.0f);
        float in1 = __fmul_rn(iw1, ih1);
        float de1 = fmaxf(__fsub_rn(__fadd_rn(areai, areaj1), in1), 1e-12f);
        bool s1 = __fdiv_rn(in1, de1) > 0.7f;

        unsigned lo = __ballot_sync(0xFFFFFFFFu, s0);
        unsigned hi = __ballot_sync(0xFFFFFFFFu, s1);
        if (lane == 0) {
            unsigned long long bits =
                (unsigned long long)lo | ((unsigned long long)hi << 32);
            if (i >= col0 + 63)  bits = 0ull;
            else if (i >= col0)  bits &= (~0ull) << (i - col0 + 1);
            g_mask[i * MW + cw] = bits;
        }
    }
}

// ---------------------------------------------------------------
__device__ __forceinline__ bool iou_gt_s(const float4 bi, float areai, const float4 bj) {
    float iw = fmaxf(__fsub_rn(fminf(bi.z, bj.z), fmaxf(bi.x, bj.x)), 0.0f);
    float ih = fmaxf(__fsub_rn(fminf(bi.w, bj.w), fmaxf(bi.y, bj.y)), 0.0f);
    float inter = __fmul_rn(iw, ih);
    float areaj = __fmul_rn(__fsub_rn(bj.z, bj.x), __fsub_rn(bj.w, bj.y));
    float denom = fmaxf(__fsub_rn(__fadd_rn(areai, areaj), inter), 1e-12f);
    return __fdiv_rn(inter, denom) > 0.7f;
}

// ---------------------------------------------------------------
// single-block NMS with 4-wide speculative batching: 4 candidate rows
// loaded per LDS round-trip, validated in strict index order in registers.
__global__ void k_nms(float* __restrict__ out) {
    extern __shared__ unsigned long long smask[];            // FASTN*MW (128KB)
    __shared__ int keptlist[TOPN];
    __shared__ unsigned long long svalid[VWORDS + 1];
    __shared__ int s_cnt;

    int tid = threadIdx.x;

    #pragma unroll
    for (int k = 0; k < MW; ++k)
        smask[k * 1024 + tid] = g_mask[k * 1024 + tid];
    if (tid < VWORDS) svalid[tid] = g_validbits[tid];
    if (tid == VWORDS) svalid[tid] = 0ull;
    __syncthreads();

    if (tid < 32) {
        const unsigned FULL = 0xFFFFFFFFu;
        int t = tid;
        int tm = t & 15;
        unsigned long long myrem = (t < MW) ? ~svalid[t] : ~0ull;

        int cnt = 0;
        int w = 0;
        unsigned long long cur = __shfl_sync(FULL, myrem, 0);
        for (;;) {
            unsigned long long avail = ~cur;
            if (avail == 0ull) {                 // uniform word transition
                ++w;
                if (w >= MW) break;
                cur = __shfl_sync(FULL, myrem, w);
                continue;
            }
            // extract up to 4 lowest available bits
            int b0 = __ffsll((long long)avail) - 1;
            unsigned long long a1 = avail & (avail - 1ull);
            unsigned long long a2 = a1 & (a1 - 1ull);
            unsigned long long a3 = a2 & (a2 - 1ull);
            bool h1 = (a1 != 0ull), h2 = (a2 != 0ull), h3 = (a3 != 0ull);
            int b1 = h1 ? __ffsll((long long)a1) - 1 : b0;
            int b2 = h2 ? __ffsll((long long)a2) - 1 : b0;
            int b3 = h3 ? __ffsll((long long)a3) - 1 : b0;
            int i0 = (w << 6) + b0;
            int i1 = (w << 6) + b1;
            int i2 = (w << 6) + b2;
            int i3 = (w << 6) + b3;

            // 8 independent LDS issued together — one latency round-trip
            unsigned long long r0 = smask[i0 * MW + w];
            unsigned long long r1 = smask[i1 * MW + w];
            unsigned long long r2 = smask[i2 * MW + w];
            unsigned long long r3 = smask[i3 * MW + w];
            unsigned long long m0 = smask[i0 * MW + tm];
            unsigned long long m1 = smask[i1 * MW + tm];
            unsigned long long m2 = smask[i2 * MW + tm];
            unsigned long long m3 = smask[i3 * MW + tm];

            // i0 always kept
            keptlist[cnt] = i0; cnt++;
            myrem |= m0;
            unsigned long long c = cur | r0 | (1ull << b0);
            if (cnt >= TOPN) { cur = c; break; }

            if (h1 && !((c >> b1) & 1ull)) {
                keptlist[cnt] = i1; cnt++;
                myrem |= m1;
                c |= r1 | (1ull << b1);
                if (cnt >= TOPN) { cur = c; break; }
            }
            if (h2 && !((c >> b2) & 1ull)) {
                keptlist[cnt] = i2; cnt++;
                myrem |= m2;
                c |= r2 | (1ull << b2);
                if (cnt >= TOPN) { cur = c; break; }
            }
            if (h3 && !((c >> b3) & 1ull)) {
                keptlist[cnt] = i3; cnt++;
                myrem |= m3;
                c |= r3 | (1ull << b3);
                if (cnt >= TOPN) { cur = c; break; }
            }
            cur = c;   // rejected bits are set in c by their suppressor's row
        }

        // deterministic fallback over candidates [FASTN, MAXC) (cold path)
        if (cnt < TOPN) {
            for (int j = FASTN; j < MAXC && cnt < TOPN; ++j) {
                if (!((svalid[j >> 6] >> (j & 63)) & 1ull)) continue;
                float4 bj = g_cboxes[j];
                bool sup = false;
                for (int k = t; k < cnt; k += 32) {
                    float4 bi = g_cboxes[keptlist[k]];
                    float areai = __fmul_rn(__fsub_rn(bi.z, bi.x), __fsub_rn(bi.w, bi.y));
                    if (iou_gt_s(bi, areai, bj)) { sup = true; break; }
                }
                if (!__any_sync(FULL, sup)) {
                    if (t == 0) keptlist[cnt] = j;
                    __syncwarp();
                    cnt++;
                }
            }
        }
        if (t == 0) s_cnt = cnt;
    }
    __syncthreads();

    int cnt = s_cnt;
    // output: proposals [300,5] then scores [300,2]
    for (int r = tid; r < TOPN; r += 1024) {
        if (r < cnt) {
            int idx = keptlist[r];
            float4 bb = g_cboxes[idx];
            float2 sc = g_cscores[idx];
            out[r*5 + 0] = 0.0f;
            out[r*5 + 1] = bb.x;
            out[r*5 + 2] = bb.y;
            out[r*5 + 3] = bb.z;
            out[r*5 + 4] = bb.w;
            out[1500 + r*2 + 0] = sc.x;
            out[1500 + r*2 + 1] = sc.y;
        } else {
            out[r*5 + 0] = 0.0f; out[r*5 + 1] = 0.0f; out[r*5 + 2] = 0.0f;
            out[r*5 + 3] = 0.0f; out[r*5 + 4] = 0.0f;
            out[1500 + r*2 + 0] = 0.0f;
            out[1500 + r*2 + 1] = 0.0f;
        }
    }

    // restore scratch invariant for next graph replay
    #pragma unroll
    for (int k = 0; k < BINS / 1024; ++k)
        g_bincnt[k * 1024 + tid] = 0;
    if (tid < VWORDS) g_validbits[tid] = 0ull;
}

// ---------------------------------------------------------------
extern "C" void kernel_launch(void* const* d_in, const int* in_sizes, int n_in,
                              void* d_out, int out_size) {
    const float* cls     = (const float*)d_in[0];
    const float* pred    = (const float*)d_in[1];
    const int*   im_info = (const int*)d_in[2];
    float* out = (float*)d_out;

    const int NMS_SMEM = FASTN * MW * (int)sizeof(unsigned long long);

    static bool attr_set = false;
    if (!attr_set) {
        cudaFuncSetAttribute(k_nms, cudaFuncAttributeMaxDynamicSharedMemorySize,
                             NMS_SMEM);
        attr_set = true;
    }

    k_prepare<<<68, 256>>>(cls, pred, im_info);
    k_rankscatter<<<64, 1024>>>();
    {
        dim3 grid(MW, 32);
        k_nmsmask1024<<<grid, 256>>>();
    }
    k_nms<<<1, 1024, NMS_SMEM>>>(out);
}